// round 5
// baseline (speedup 1.0000x reference)
#include <cuda_runtime.h>
#include <cstdint>

#define N_NODESC 100000
#define N_EDGESC 2500000
#define IN_CH 32
#define HID 16
#define OUT_CH 64
#define NUM_GRAPHS 64

#define SCAN_BLK 1024
#define NSCAN_BLOCKS ((N_NODESC + SCAN_BLK - 1) / SCAN_BLK)   // 98

// ---------------- scratch ----------------
__device__ __align__(16) float g_y[N_NODESC * HID];    // x @ w1_l^T
__device__ __align__(16) float g_xr[N_NODESC * HID];   // x @ w1_r^T
__device__ __align__(16) float g_h1[N_NODESC * HID];   // layer-1 output
__device__ __align__(16) float g_m2[N_NODESC * HID];   // layer-2 mean aggregate
__device__ __align__(16) float g_gacc[NUM_GRAPHS * OUT_CH];
__device__ __align__(16) float g_gcnt[NUM_GRAPHS];
__device__ int g_deg[N_NODESC];
__device__ int g_start[N_NODESC];
__device__ int g_cursor[N_NODESC];
__device__ int g_part[SCAN_BLK];        // block partials (NSCAN_BLOCKS used)
__device__ int g_csr[N_EDGESC];         // src ids grouped by dst

__device__ __forceinline__ void red_add_v4(float* p, float a, float b, float c, float d) {
    asm volatile("red.global.add.v4.f32 [%0], {%1, %2, %3, %4};"
                 :: "l"(p), "f"(a), "f"(b), "f"(c), "f"(d) : "memory");
}

// ---------------- Kernel A: pre-transform x -> y, xr; zero deg + graph accum ----------------
__global__ void __launch_bounds__(256) kPre(const float* __restrict__ x,
                                            const float* __restrict__ w1l,
                                            const float* __restrict__ w1r) {
    __shared__ __align__(16) float swl[HID * IN_CH];
    __shared__ __align__(16) float swr[HID * IN_CH];
    int t = threadIdx.x;
    for (int i = t; i < HID * IN_CH; i += blockDim.x) {
        swl[i] = w1l[i];
        swr[i] = w1r[i];
    }
    __syncthreads();

    int n = blockIdx.x * blockDim.x + t;
    if (n >= N_NODESC) return;

    g_deg[n] = 0;
    if (n < NUM_GRAPHS * OUT_CH) g_gacc[n] = 0.0f;
    if (n < NUM_GRAPHS) g_gcnt[n] = 0.0f;

    float xv[IN_CH];
    const float4* xp = reinterpret_cast<const float4*>(x + (size_t)n * IN_CH);
#pragma unroll
    for (int i = 0; i < IN_CH / 4; i++) {
        float4 v = __ldg(xp + i);
        xv[4*i+0] = v.x; xv[4*i+1] = v.y; xv[4*i+2] = v.z; xv[4*i+3] = v.w;
    }

    float yl[HID], yr[HID];
#pragma unroll
    for (int o = 0; o < HID; o++) {
        float al = 0.0f, ar = 0.0f;
#pragma unroll
        for (int kk = 0; kk < IN_CH / 4; kk++) {
            float4 wl = *reinterpret_cast<float4*>(&swl[o * IN_CH + kk * 4]);
            float4 wr = *reinterpret_cast<float4*>(&swr[o * IN_CH + kk * 4]);
            al += xv[kk*4+0]*wl.x + xv[kk*4+1]*wl.y + xv[kk*4+2]*wl.z + xv[kk*4+3]*wl.w;
            ar += xv[kk*4+0]*wr.x + xv[kk*4+1]*wr.y + xv[kk*4+2]*wr.z + xv[kk*4+3]*wr.w;
        }
        yl[o] = al; yr[o] = ar;
    }

    float4* yp = reinterpret_cast<float4*>(g_y  + (size_t)n * HID);
    float4* rp = reinterpret_cast<float4*>(g_xr + (size_t)n * HID);
#pragma unroll
    for (int i = 0; i < HID / 4; i++) {
        yp[i] = make_float4(yl[4*i], yl[4*i+1], yl[4*i+2], yl[4*i+3]);
        rp[i] = make_float4(yr[4*i], yr[4*i+1], yr[4*i+2], yr[4*i+3]);
    }
}

// ---------------- CSR build ----------------
__global__ void __launch_bounds__(256) kDeg(const int* __restrict__ ei) {
    int e = blockIdx.x * blockDim.x + threadIdx.x;
    if (e >= N_EDGESC) return;
    atomicAdd(&g_deg[__ldg(&ei[N_EDGESC + e])], 1);
}

__global__ void __launch_bounds__(SCAN_BLK) kScan1() {
    __shared__ int sh[SCAN_BLK];
    int t = threadIdx.x;
    int i = blockIdx.x * SCAN_BLK + t;
    int v = (i < N_NODESC) ? g_deg[i] : 0;
    sh[t] = v;
    __syncthreads();
    for (int off = 1; off < SCAN_BLK; off <<= 1) {
        int add = (t >= off) ? sh[t - off] : 0;
        __syncthreads();
        sh[t] += add;
        __syncthreads();
    }
    if (i < N_NODESC) g_start[i] = sh[t] - v;          // exclusive
    if (t == SCAN_BLK - 1) g_part[blockIdx.x] = sh[t]; // block total
}

__global__ void __launch_bounds__(128) kScan2() {
    __shared__ int sh[128];
    int t = threadIdx.x;
    int v = (t < NSCAN_BLOCKS) ? g_part[t] : 0;
    sh[t] = v;
    __syncthreads();
    for (int off = 1; off < 128; off <<= 1) {
        int add = (t >= off) ? sh[t - off] : 0;
        __syncthreads();
        sh[t] += add;
        __syncthreads();
    }
    g_part[t] = sh[t] - v;                             // exclusive
}

__global__ void __launch_bounds__(SCAN_BLK) kScan3() {
    int i = blockIdx.x * SCAN_BLK + threadIdx.x;
    if (i >= N_NODESC) return;
    int s = g_start[i] + g_part[blockIdx.x];
    g_start[i] = s;
    g_cursor[i] = s;
}

__global__ void __launch_bounds__(256) kPlace(const int* __restrict__ ei) {
    int e = blockIdx.x * blockDim.x + threadIdx.x;
    if (e >= N_EDGESC) return;
    int s = __ldg(&ei[e]);
    int d = __ldg(&ei[N_EDGESC + e]);
    int pos = atomicAdd(&g_cursor[d], 1);
    g_csr[pos] = s;
}

// ---------------- Aggregation: warp per node, quad per edge, shfl-tree reduce ----------------
// mode 0: layer1 -> h1 = relu(mean(y) + b1 + xr)
// mode 1: layer2 -> m2 = mean(h1)
template <int MODE>
__global__ void __launch_bounds__(256) kAgg(const float* __restrict__ val,
                                            const float* __restrict__ b1,
                                            float* __restrict__ outp) {
    int warp = (blockIdx.x * blockDim.x + threadIdx.x) >> 5;
    if (warp >= N_NODESC) return;
    int lane = threadIdx.x & 31;
    int c = lane & 3;          // 16B chunk within 64B row
    int eoff = lane >> 2;      // edge slot within batch of 8

    int start = __ldg(&g_start[warp]);
    int deg   = __ldg(&g_deg[warp]);

    float4 acc = make_float4(0.f, 0.f, 0.f, 0.f);
    for (int b = 0; b < deg; b += 8) {
        int el = b + eoff;
        bool ok = el < deg;
        int src = ok ? __ldg(&g_csr[start + el]) : 0;
        if (ok) {
            float4 v = __ldg(reinterpret_cast<const float4*>(val + (size_t)src * HID) + c);
            acc.x += v.x; acc.y += v.y; acc.z += v.z; acc.w += v.w;
        }
    }
    // sum over the 8 edge slots (strides 4, 8, 16); chunk id c preserved
#pragma unroll
    for (int st = 4; st <= 16; st <<= 1) {
        acc.x += __shfl_xor_sync(0xffffffffu, acc.x, st);
        acc.y += __shfl_xor_sync(0xffffffffu, acc.y, st);
        acc.z += __shfl_xor_sync(0xffffffffu, acc.z, st);
        acc.w += __shfl_xor_sync(0xffffffffu, acc.w, st);
    }

    if (lane < 4) {
        float inv = 1.0f / fmaxf((float)deg, 1.0f);
        float4 m = make_float4(acc.x * inv, acc.y * inv, acc.z * inv, acc.w * inv);
        if (MODE == 0) {
            float4 bb = __ldg(reinterpret_cast<const float4*>(b1) + c);
            float4 r  = *reinterpret_cast<const float4*>(&g_xr[(size_t)warp * HID + c * 4]);
            m.x = fmaxf(m.x + bb.x + r.x, 0.0f);
            m.y = fmaxf(m.y + bb.y + r.y, 0.0f);
            m.z = fmaxf(m.z + bb.z + r.z, 0.0f);
            m.w = fmaxf(m.w + bb.w + r.w, 0.0f);
        }
        *reinterpret_cast<float4*>(outp + (size_t)warp * HID + c * 4) = m;
    }
}

// ---------------- Kernel E: node GEMV + warp-aggregated graph readout ----------------
__global__ void __launch_bounds__(128) kLayer2(const int* __restrict__ batch,
                                               const float* __restrict__ w2l,
                                               const float* __restrict__ b2,
                                               const float* __restrict__ w2r) {
    __shared__ __align__(16) float swl[HID * OUT_CH];   // transposed [k][o]
    __shared__ __align__(16) float swr[HID * OUT_CH];
    __shared__ __align__(16) float sb2[OUT_CH];
    int t = threadIdx.x;
    for (int i = t; i < HID * OUT_CH; i += blockDim.x) {
        int o = i / HID, k = i % HID;
        swl[k * OUT_CH + o] = w2l[i];
        swr[k * OUT_CH + o] = w2r[i];
    }
    for (int i = t; i < OUT_CH; i += blockDim.x) sb2[i] = b2[i];
    __syncthreads();

    int n = blockIdx.x * blockDim.x + t;
    bool valid = n < N_NODESC;
    int nn = valid ? n : (N_NODESC - 1);
    int lane = t & 31;

    float av[HID], hv[HID];
    const float4* ap = reinterpret_cast<const float4*>(g_m2 + (size_t)nn * HID);
    const float4* hp = reinterpret_cast<const float4*>(g_h1 + (size_t)nn * HID);
#pragma unroll
    for (int i = 0; i < HID / 4; i++) {
        float4 a = ap[i];
        av[4*i] = a.x; av[4*i+1] = a.y; av[4*i+2] = a.z; av[4*i+3] = a.w;
        float4 h = hp[i];
        hv[4*i] = h.x; hv[4*i+1] = h.y; hv[4*i+2] = h.z; hv[4*i+3] = h.w;
    }

    float acc[OUT_CH];
#pragma unroll
    for (int o = 0; o < OUT_CH; o++) acc[o] = sb2[o];

#pragma unroll
    for (int k = 0; k < HID; k++) {
        float ak = av[k], hk = hv[k];
#pragma unroll
        for (int o = 0; o < OUT_CH; o += 4) {
            float4 wl = *reinterpret_cast<float4*>(&swl[k * OUT_CH + o]);
            float4 wr = *reinterpret_cast<float4*>(&swr[k * OUT_CH + o]);
            acc[o + 0] += ak * wl.x + hk * wr.x;
            acc[o + 1] += ak * wl.y + hk * wr.y;
            acc[o + 2] += ak * wl.z + hk * wr.z;
            acc[o + 3] += ak * wl.w + hk * wr.w;
        }
    }

    if (!valid) {
#pragma unroll
        for (int o = 0; o < OUT_CH; o++) acc[o] = 0.0f;
    }

    int g = __ldg(&batch[nn]);
    int g0 = __shfl_sync(0xffffffffu, g, 0);
    bool uni = __all_sync(0xffffffffu, g == g0);
    int nvalid = __popc(__ballot_sync(0xffffffffu, valid));

    if (uni) {
#pragma unroll
        for (int o = 0; o < OUT_CH; o++) {
            float v = acc[o];
            v += __shfl_xor_sync(0xffffffffu, v, 16);
            v += __shfl_xor_sync(0xffffffffu, v, 8);
            v += __shfl_xor_sync(0xffffffffu, v, 4);
            v += __shfl_xor_sync(0xffffffffu, v, 2);
            v += __shfl_xor_sync(0xffffffffu, v, 1);
            acc[o] = v;
        }
        if (lane == 0 && nvalid > 0) {
            float* gp = g_gacc + (size_t)g0 * OUT_CH;
#pragma unroll
            for (int o = 0; o < OUT_CH; o += 4)
                red_add_v4(gp + o, acc[o], acc[o + 1], acc[o + 2], acc[o + 3]);
            atomicAdd(&g_gcnt[g0], (float)nvalid);
        }
    } else if (valid) {
        float* gp = g_gacc + (size_t)g * OUT_CH;
#pragma unroll
        for (int o = 0; o < OUT_CH; o += 4)
            red_add_v4(gp + o, acc[o], acc[o + 1], acc[o + 2], acc[o + 3]);
        atomicAdd(&g_gcnt[g], 1.0f);
    }
}

// ---------------- Kernel F: final divide into d_out ----------------
__global__ void __launch_bounds__(256) kFinal(float* __restrict__ out) {
    int i = blockIdx.x * blockDim.x + threadIdx.x;
    if (i >= NUM_GRAPHS * OUT_CH) return;
    out[i] = g_gacc[i] / fmaxf(g_gcnt[i >> 6], 1.0f);
}

// ---------------- launch ----------------
extern "C" void kernel_launch(void* const* d_in, const int* in_sizes, int n_in,
                              void* d_out, int out_size) {
    const float* x    = (const float*)d_in[0];
    const int*   ei   = (const int*)d_in[1];
    const int*   batch= (const int*)d_in[2];
    const float* w1l  = (const float*)d_in[3];
    const float* b1   = (const float*)d_in[4];
    const float* w1r  = (const float*)d_in[5];
    const float* w2l  = (const float*)d_in[6];
    const float* b2   = (const float*)d_in[7];
    const float* w2r  = (const float*)d_in[8];
    float* out = (float*)d_out;

    float* gy;  cudaGetSymbolAddress((void**)&gy,  g_y);
    float* gh1; cudaGetSymbolAddress((void**)&gh1, g_h1);
    float* gm2; cudaGetSymbolAddress((void**)&gm2, g_m2);

    const int TB = 256;
    int nodeBlocks = (N_NODESC + TB - 1) / TB;
    int edgeBlocks = (N_EDGESC + TB - 1) / TB;
    int aggBlocks  = (N_NODESC * 32 + TB - 1) / TB;   // warp per node

    kPre<<<nodeBlocks, TB>>>(x, w1l, w1r);
    kDeg<<<edgeBlocks, TB>>>(ei);
    kScan1<<<NSCAN_BLOCKS, SCAN_BLK>>>();
    kScan2<<<1, 128>>>();
    kScan3<<<NSCAN_BLOCKS, SCAN_BLK>>>();
    kPlace<<<edgeBlocks, TB>>>(ei);
    kAgg<0><<<aggBlocks, TB>>>(gy, b1, gh1);
    kAgg<1><<<aggBlocks, TB>>>(gh1, b1, gm2);
    kLayer2<<<(N_NODESC + 127) / 128, 128>>>(batch, w2l, b2, w2r);
    kFinal<<<(NUM_GRAPHS * OUT_CH + TB - 1) / TB, TB>>>(out);
}